// round 16
// baseline (speedup 1.0000x reference)
#include <cuda_runtime.h>

// LIF, exact k=8 renewal-group folding, HT=256 tiles (128 barriers), 8 warps
// with pipe-aware SMSP placement (fix for R15's scheduler overload).
//
// Exact step: f = set.le(S,th); S = fma(S,f,x)   (bit-exact, proven R4..R15).
// Group of 8 (entry S=u0, inputs x1..x8):
//   u_i = u_{i-1} + x_i  (i=1..7)            speculative no-spike FADD chain
//   a   = fma(u7, [u7<=th], x8)              exact step-8 fold
//   first crossing j = min{ i in 0..6 : u_i > th }  ->  T_j  (exact restart
//   tails from helpers, exact STEPX recurrence), else a. 3-level priority
//   select tree — identical first-crossing semantics as proven k=4/k=8.
//
// 32 blocks = 16 batches x 2 neuron-halves (32 chains). 256 threads; wid%4
// is the SMSP:
//   wid7 : chain warp (SMSP3)            — fma/latency-bound
//   wid3 : drain half B (SMSP3)          — LSU-bound, complements chain
//   wid0,1,2 : T-table helpers (SMSP0-2) — groups grp%3==wid
//   wid4,5   : rerun warps (SMSP0,1)     — also stage x tile t+2
//   wid6     : drain half A (SMSP2)
// One __syncthreads per 256-step tile (128 barriers). 144KB dynamic smem.

#define NB 16
#define NS 256
#define NH 128
#define NN 64
#define NPB 32
#define HT 256
#define NTILES 128
#define GPT 32                      // k=8 groups per tile
#define RS 260                      // sbuf row stride
#define TT (NS * NH)
#define TOTE ((long long)NB * NS * NN * NH)

// dynamic smem layout (float offsets)
#define OFF_TQ   0                               // float4[2][GPT][2][NPB] = 16384 f
#define OFF_ENT  16384                           // float [2][GPT][NPB]    = 2048 f
#define OFF_SBUF (OFF_ENT + 2048)                // float [2][NPB*RS]      = 16640 f
#define OFF_XS   (OFF_SBUF + 2 * NPB * RS)       // float [4][HT]          = 1024 f
#define OFF_THR  (OFF_XS + 4 * HT)               // float [NPB]            = 32 f
#define SMEM_FLOATS (OFF_THR + NPB)
#define SMEM_BYTES  (SMEM_FLOATS * 4)            // 144512 B

#define STEPX(S, XV, TH) do {                                               \
    float f_;                                                               \
    asm("set.le.f32.f32 %0, %1, %2;" : "=f"(f_) : "f"(S), "f"(TH));         \
    asm("fma.rn.f32 %0, %1, %2, %3;" : "=f"(S) : "f"(S), "f"(f_), "f"(XV)); \
} while (0)

// helper body: T tables for tile slot `dst` from x row `xr`, groups grp%3==hidx
#define HELPER_BODY(xr, Td, hidx)                                           \
    do {                                                                    \
        _Pragma("unroll")                                                   \
        for (int gg = 0; gg < 11; ++gg) {                                   \
            const int grp = gg * 3 + (hidx);                                \
            if (grp < GPT) {                                                \
                float xv[8];                                                \
                *(float4*)&xv[0] = *(const float4*)&(xr)[grp * 8];          \
                *(float4*)&xv[4] = *(const float4*)&(xr)[grp * 8 + 4];      \
                float Tv[7];                                                \
                _Pragma("unroll")                                           \
                for (int j = 6; j >= 0; --j) {                              \
                    float P = xv[j];                                        \
                    _Pragma("unroll")                                       \
                    for (int i = j + 1; i < 8; ++i) STEPX(P, xv[i], th);    \
                    Tv[j] = P;                                              \
                }                                                           \
                (Td)[(grp * 2 + 0) * NPB + lane] =                          \
                    make_float4(Tv[0], Tv[1], Tv[2], Tv[3]);                \
                (Td)[(grp * 2 + 1) * NPB + lane] =                          \
                    make_float4(Tv[4], Tv[5], Tv[6], 0.0f);                 \
            }                                                               \
        }                                                                   \
    } while (0)

__global__ __launch_bounds__(256, 1)
void lif_kernel(const float* __restrict__ inputs,
                const float* __restrict__ threshes,
                const float* __restrict__ acc0,
                float* __restrict__ outbuf)
{
    extern __shared__ float smem[];
    float4* const Tq   = (float4*)(smem + OFF_TQ);    // [2][GPT][2][NPB]
    float*  const ent  = smem + OFF_ENT;              // [2][GPT][NPB]
    float*  const sbuf = smem + OFF_SBUF;             // [2][NPB*RS]
    float*  const xs   = smem + OFF_XS;               // [4][HT]
    float*  const thr  = smem + OFF_THR;              // [NPB]

    const int b    = blockIdx.x >> 1;
    const int g    = blockIdx.x & 1;
    const int tid  = threadIdx.x;
    const int wid  = tid >> 5;
    const int lane = tid & 31;
    const float* xb = inputs + (long long)b * TT;
    float* outp = outbuf;

    // ---- prologue 1: stage x(0), x(1); thresholds ----
    if (wid == 4) {
        *(float4*)&xs[0 * HT + lane * 4]       = *(const float4*)(xb + lane * 4);
        *(float4*)&xs[0 * HT + 128 + lane * 4] = *(const float4*)(xb + 128 + lane * 4);
    }
    if (wid == 5) {
        *(float4*)&xs[1 * HT + lane * 4]       = *(const float4*)(xb + HT + lane * 4);
        *(float4*)&xs[1 * HT + 128 + lane * 4] = *(const float4*)(xb + HT + 128 + lane * 4);
    }
    if (wid == 6) thr[lane] = threshes[g * NPB + lane];
    __syncthreads();

    const float th = thr[lane];              // lane == chain index in all roles

    // ---- prologue 2: T(0) by helpers; chain loads acc0 ----
    float S = 0.0f;
    if (wid <= 2) {
        const float* __restrict__ xr0 = xs;  // tile 0
        float4* __restrict__ Td0 = Tq;       // slot 0
        HELPER_BODY(xr0, Td0, wid);
    }
    if (wid == 7) S = acc0[b * NN + g * NPB + lane];
    __syncthreads();

    for (int t = 0; t <= NTILES + 1; ++t) {
        if (wid == 7) {
            // ================= chain warp: tile t (SMSP3) =================
            if (t < NTILES) {
                const float*  __restrict__ xr = xs + (t & 3) * HT;
                const float4* __restrict__ Tt = Tq + (t & 1) * GPT * 2 * NPB;
                float* __restrict__ ed = ent + (t & 1) * GPT * NPB;
                #pragma unroll
                for (int grp = 0; grp < GPT; ++grp) {
                    float4 xa = *(const float4*)&xr[grp * 8];       // broadcast
                    float4 xc = *(const float4*)&xr[grp * 8 + 4];
                    float4 TA = Tt[(grp * 2 + 0) * NPB + lane];     // LDS.128
                    float4 TB = Tt[(grp * 2 + 1) * NPB + lane];
                    ed[grp * NPB + lane] = S;                       // group entry
                    float u1 = S  + xa.x;
                    float u2 = u1 + xa.y;
                    float u3 = u2 + xa.z;
                    float u4 = u3 + xa.w;
                    float u5 = u4 + xc.x;
                    float u6 = u5 + xc.y;
                    float u7 = u6 + xc.z;
                    float Sn;
                    asm("{\n\t"
                        ".reg .pred m0,m2,m4,m6,m01,m23,m45,m0123;\n\t"
                        ".reg .f32  f7,a,s01,s23,s45,s6a,sA,sB;\n\t"
                        "setp.gt.f32 m0, %1, %2;\n\t"          // u0 > th
                        "setp.gt.or.f32 m01, %3, %2, m0;\n\t"  // |u1>th
                        "setp.gt.f32 m2, %4, %2;\n\t"          // u2 > th
                        "setp.gt.or.f32 m23, %5, %2, m2;\n\t"  // |u3>th
                        "setp.gt.f32 m4, %6, %2;\n\t"          // u4 > th
                        "setp.gt.or.f32 m45, %7, %2, m4;\n\t"  // |u5>th
                        "setp.gt.f32 m6, %8, %2;\n\t"          // u6 > th
                        "or.pred m0123, m01, m23;\n\t"
                        "set.le.f32.f32 f7, %9, %2;\n\t"       // [u7<=th]
                        "fma.rn.f32 a, %9, f7, %10;\n\t"       // exact step-8 fold
                        "selp.f32 s01, %11, %12, m0;\n\t"      // m0?T0:T1
                        "selp.f32 s23, %13, %14, m2;\n\t"      // m2?T2:T3
                        "selp.f32 s45, %15, %16, m4;\n\t"      // m4?T4:T5
                        "selp.f32 s6a, %17, a, m6;\n\t"        // m6?T6:a
                        "selp.f32 sA, s01, s23, m01;\n\t"
                        "selp.f32 sB, s45, s6a, m45;\n\t"
                        "selp.f32 %0, sA, sB, m0123;\n\t"      // priority root
                        "}"
                        : "=f"(Sn)
                        : "f"(S), "f"(th), "f"(u1), "f"(u2), "f"(u3),
                          "f"(u4), "f"(u5), "f"(u6), "f"(u7), "f"(xc.w),
                          "f"(TA.x), "f"(TA.y), "f"(TA.z), "f"(TA.w),
                          "f"(TB.x), "f"(TB.y), "f"(TB.z));
                    S = Sn;
                }
            }
        } else if (wid <= 2) {
            // ============ T helpers (SMSP0-2): tile t+1 ============
            if (t + 1 < NTILES) {
                const float* __restrict__ xr = xs + ((t + 1) & 3) * HT;
                float4* __restrict__ Td = Tq + ((t + 1) & 1) * GPT * 2 * NPB;
                HELPER_BODY(xr, Td, wid);
            }
        } else if (wid == 4 || wid == 5) {
            // ===== rerun warps (SMSP0,1): tile t-1 -> sbuf; stage x(t+2) =====
            if (t + 2 < NTILES) {
                const float* src = xb + (t + 2) * HT;
                float* dst = &xs[((t + 2) & 3) * HT];
                const int h0 = (wid - 4) * 128;
                *(float4*)&dst[h0 + lane * 4] = *(const float4*)(src + h0 + lane * 4);
            }
            if (t >= 1 && t <= NTILES) {
                const int par = wid - 4;
                const int pt  = (t - 1) & 1;
                const float* __restrict__ xr = xs + ((t - 1) & 3) * HT;
                const float* __restrict__ ed = ent + pt * GPT * NPB;
                float* __restrict__ sb = sbuf + pt * NPB * RS;
                #pragma unroll
                for (int gg = 0; gg < 16; ++gg) {
                    const int grp = gg * 2 + par;
                    float  P  = ed[grp * NPB + lane];
                    float4 xa = *(const float4*)&xr[grp * 8];
                    float4 xc = *(const float4*)&xr[grp * 8 + 4];
                    float4 o1, o2;
                    STEPX(P, xa.x, th); o1.x = P;
                    STEPX(P, xa.y, th); o1.y = P;
                    STEPX(P, xa.z, th); o1.z = P;
                    STEPX(P, xa.w, th); o1.w = P;
                    STEPX(P, xc.x, th); o2.x = P;
                    STEPX(P, xc.y, th); o2.y = P;
                    STEPX(P, xc.z, th); o2.z = P;
                    STEPX(P, xc.w, th); o2.w = P;
                    *(float4*)&sb[lane * RS + grp * 8]     = o1;   // STS.128
                    *(float4*)&sb[lane * RS + grp * 8 + 4] = o2;
                }
            }
        } else if (wid == 3 || wid == 6) {
            // ===== drain warps (SMSP3,2): sbuf tile t-2 -> global =====
            if (t >= 2) {
                const int dt = t - 2;                 // tile covers s = 2dt, 2dt+1
                const int pt = dt & 1;
                const int idx0 = (wid == 3) ? 0 : 1024;
                const float* __restrict__ sb = sbuf + pt * NPB * RS;
                #pragma unroll
                for (int i = 0; i < 32; ++i) {
                    int idx = idx0 + i * 32 + lane;   // 0..2047
                    int sl  = idx >> 10;              // s_local 0/1
                    int rem = idx & 1023;
                    int n = rem >> 5, q = rem & 31;
                    float4 v = *(const float4*)&sb[n * RS + sl * 128 + q * 4];
                    float tn = thr[n];
                    float f0, f1, f2, f3;
                    asm("set.gt.f32.f32 %0, %1, %2;" : "=f"(f0) : "f"(v.x), "f"(tn));
                    asm("set.gt.f32.f32 %0, %1, %2;" : "=f"(f1) : "f"(v.y), "f"(tn));
                    asm("set.gt.f32.f32 %0, %1, %2;" : "=f"(f2) : "f"(v.z), "f"(tn));
                    asm("set.gt.f32.f32 %0, %1, %2;" : "=f"(f3) : "f"(v.w), "f"(tn));
                    float4 o = make_float4(v.x * f0, v.y * f1, v.z * f2, v.w * f3);
                    float4 k = make_float4(f0, f1, f2, f3);
                    float* ob = outp +
                        (((long long)b * NS + dt * 2 + sl) * NN + g * NPB + n) * NH;
                    *(float4*)(ob + q * 4)        = o;   // STG.128 coalesced
                    *(float4*)(ob + TOTE + q * 4) = k;
                }
            }
        }
        __syncthreads();
    }
}

extern "C" void kernel_launch(void* const* d_in, const int* in_sizes, int n_in,
                              void* d_out, int out_size)
{
    const float* inputs   = (const float*)d_in[0];  // [B,S,H]
    const float* threshes = (const float*)d_in[1];  // [N]
    const float* acc0     = (const float*)d_in[2];  // [B,N]
    float* out = (float*)d_out;                     // outs then spikes (f32)

    cudaFuncSetAttribute(lif_kernel,
                         cudaFuncAttributeMaxDynamicSharedMemorySize,
                         SMEM_BYTES);
    lif_kernel<<<NB * 2, 256, SMEM_BYTES>>>(inputs, threshes, acc0, out);
}

// round 17
// speedup vs baseline: 1.1328x; 1.1328x over previous
#include <cuda_runtime.h>

// LIF, exact k=4 renewal-group folding, HT=128 tiles — R14 winner (209.6us)
// with ONE change: the chain warp software-pipelines its Tv/xq shared loads
// one group ahead, hiding the ~29-cyc LDS latency that post-mortem R16
// identified as the missing ~13 cyc/group on the serial chain.
//
// Exact step: f = set.le(S,th); S = fma(S,f,x)  (bit-exact, proven R4..R16).
// Group of 4 (entry S, inputs x1..x4):
//   u1=S+x1; u2=u1+x2; u3=u2+x3              speculative no-spike FADDs
//   a  = fma(u3, [u3<=th], x4)               exact step-4 fold
//   r  = m01 ? (m0?T0:T1) : (m2?T2:a)        priority tree (first crossing)
// T_k = exact restart tails from helper warps (exact STEPX recurrence).
//
// 32 blocks = 16 batches x 2 neuron-halves (32 chains). 256 threads:
//   wid4  : chain warp, 32 groups/tile, prefetched operands
//   wid5,6: T-table helpers for tile t+1 (even/odd groups)
//   wid1,2: rerun warps: exact per-step S of tile t-1 -> sbuf (STS.128)
//   wid3,7: drain warps: sbuf tile t-2 -> global, h-contiguous STG.128
//   wid0  : x stager (tile t+2)
// One __syncthreads per 128-step tile (256 barriers). 77KB dynamic smem.

#define NB 16
#define NS 256
#define NH 128
#define NN 64
#define NPB 32
#define HT 128
#define NTILES 256
#define GPT 32                      // k=4 groups per tile
#define RS 132                      // sbuf row stride: 16B chunk 33n+q, conflict-free
#define TT (NS * NH)
#define TOTE ((long long)NB * NS * NN * NH)

// dynamic smem layout (float offsets)
#define OFF_TQ   0                               // float4[2][GPT][NPB] = 8192 f
#define OFF_ENT  8192                            // float [2][GPT][NPB] = 2048 f
#define OFF_SBUF (OFF_ENT + 2048)                // float [2][NPB*RS]   = 8448 f
#define OFF_XS   (OFF_SBUF + 2 * NPB * RS)       // float [4][HT]       = 512 f
#define OFF_THR  (OFF_XS + 4 * HT)               // float [NPB]         = 32 f
#define SMEM_FLOATS (OFF_THR + NPB)
#define SMEM_BYTES  (SMEM_FLOATS * 4)            // 76928 B

#define STEPX(S, XV, TH) do {                                               \
    float f_;                                                               \
    asm("set.le.f32.f32 %0, %1, %2;" : "=f"(f_) : "f"(S), "f"(TH));         \
    asm("fma.rn.f32 %0, %1, %2, %3;" : "=f"(S) : "f"(S), "f"(f_), "f"(XV)); \
} while (0)

__global__ __launch_bounds__(256, 1)
void lif_kernel(const float* __restrict__ inputs,
                const float* __restrict__ threshes,
                const float* __restrict__ acc0,
                float* __restrict__ outbuf)
{
    extern __shared__ float smem[];
    float4* const Tq   = (float4*)(smem + OFF_TQ);    // [2][GPT][NPB]
    float*  const ent  = smem + OFF_ENT;              // [2][GPT][NPB]
    float*  const sbuf = smem + OFF_SBUF;             // [2][NPB*RS]
    float*  const xs   = smem + OFF_XS;               // [4][HT]
    float*  const thr  = smem + OFF_THR;              // [NPB]

    const int b    = blockIdx.x >> 1;
    const int g    = blockIdx.x & 1;
    const int tid  = threadIdx.x;
    const int wid  = tid >> 5;
    const int lane = tid & 31;
    const float* xb = inputs + (long long)b * TT;
    float* outp = outbuf;

    // ---- prologue 1: stage x(0), x(1); thresholds ----
    if (wid == 0)
        *(float4*)&xs[0 * HT + lane * 4] = *(const float4*)(xb + lane * 4);
    if (wid == 3)
        *(float4*)&xs[1 * HT + lane * 4] = *(const float4*)(xb + HT + lane * 4);
    if (wid == 1) thr[lane] = threshes[g * NPB + lane];
    __syncthreads();

    const float th = thr[lane];              // lane == chain index in all roles

    // ---- prologue 2: T(0); chain loads acc0 ----
    float S = 0.0f;
    if (wid == 5 || wid == 6) {
        const int par = wid - 5;
        #pragma unroll
        for (int gg = 0; gg < 16; ++gg) {
            const int grp = gg * 2 + par;
            float4 xq = *(const float4*)&xs[0 * HT + grp * 4];
            float T2 = xq.z;  STEPX(T2, xq.w, th);
            float T1 = xq.y;  STEPX(T1, xq.z, th);  STEPX(T1, xq.w, th);
            float T0 = xq.x;  STEPX(T0, xq.y, th);  STEPX(T0, xq.z, th);
            STEPX(T0, xq.w, th);
            Tq[(0 * GPT + grp) * NPB + lane] = make_float4(T0, T1, T2, 0.0f);
        }
    }
    if (wid == 4) S = acc0[b * NN + g * NPB + lane];
    __syncthreads();

    for (int t = 0; t <= NTILES + 1; ++t) {
        if (wid == 4) {
            // ===== chain warp: tile t, one-group-ahead operand prefetch =====
            if (t < NTILES) {
                const float*  __restrict__ xr = xs + (t & 3) * HT;
                const float4* __restrict__ Tt = Tq + (t & 1) * GPT * NPB;
                float* __restrict__ ed = ent + (t & 1) * GPT * NPB;
                float4 Tv = Tt[lane];                        // grp 0 operands
                float4 xq = *(const float4*)&xr[0];
                #pragma unroll
                for (int grp = 0; grp < GPT; ++grp) {
                    float4 Tn, xn;
                    if (grp + 1 < GPT) {                     // prefetch grp+1:
                        Tn = Tt[(grp + 1) * NPB + lane];     // issues before the
                        xn = *(const float4*)&xr[(grp + 1) * 4];  // ALU tail, no
                    }                                        // dependence on S
                    ed[grp * NPB + lane] = S;                // group entry
                    float u1 = S + xq.x;
                    float u2 = u1 + xq.y;
                    float u3 = u2 + xq.z;
                    float Sn;
                    asm("{\n\t"
                        ".reg .pred m0, m01, m2;\n\t"
                        ".reg .f32  f3, a, sl, inr;\n\t"
                        "setp.gt.f32 m0, %1, %2;\n\t"         // S  > th
                        "setp.gt.or.f32 m01, %3, %2, m0;\n\t" // u1 > th | m0
                        "setp.gt.f32 m2, %4, %2;\n\t"         // u2 > th
                        "set.le.f32.f32 f3, %5, %2;\n\t"      // [u3 <= th]
                        "fma.rn.f32 a, %5, f3, %6;\n\t"       // exact step-4 fold
                        "selp.f32 sl, %7, %8, m0;\n\t"        // m0 ? T0 : T1
                        "selp.f32 inr, %9, a, m2;\n\t"        // m2 ? T2 : a
                        "selp.f32 %0, sl, inr, m01;\n\t"      // priority root
                        "}"
                        : "=f"(Sn)
                        : "f"(S), "f"(th), "f"(u1), "f"(u2), "f"(u3),
                          "f"(xq.w), "f"(Tv.x), "f"(Tv.y), "f"(Tv.z));
                    S = Sn;
                    Tv = Tn;                                  // rotate prefetch
                    xq = xn;
                }
            }
        } else if (wid == 0) {
            // ================= x stager: tile t+2 =================
            if (t + 2 < NTILES)
                *(float4*)&xs[((t + 2) & 3) * HT + lane * 4] =
                    *(const float4*)(xb + (t + 2) * HT + lane * 4);
        } else if (wid == 5 || wid == 6) {
            // ================= T helpers: tile t+1 =================
            if (t + 1 < NTILES) {
                const int par = wid - 5;
                const float* __restrict__ xr = xs + ((t + 1) & 3) * HT;
                float4* __restrict__ Td = Tq + ((t + 1) & 1) * GPT * NPB;
                #pragma unroll
                for (int gg = 0; gg < 16; ++gg) {
                    const int grp = gg * 2 + par;
                    float4 xq = *(const float4*)&xr[grp * 4];
                    float T2 = xq.z;  STEPX(T2, xq.w, th);
                    float T1 = xq.y;  STEPX(T1, xq.z, th);  STEPX(T1, xq.w, th);
                    float T0 = xq.x;  STEPX(T0, xq.y, th);  STEPX(T0, xq.z, th);
                    STEPX(T0, xq.w, th);
                    Td[grp * NPB + lane] = make_float4(T0, T1, T2, 0.0f);
                }
            }
        } else if (wid == 1 || wid == 2) {
            // ================= rerun warps: tile t-1 -> sbuf =================
            if (t >= 1 && t <= NTILES) {
                const int par = wid - 1;
                const int pt  = (t - 1) & 1;
                const float* __restrict__ xr = xs + ((t - 1) & 3) * HT;
                const float* __restrict__ ed = ent + pt * GPT * NPB;
                float* __restrict__ sb = sbuf + pt * NPB * RS;
                #pragma unroll
                for (int gg = 0; gg < 16; ++gg) {
                    const int grp = gg * 2 + par;
                    float  P  = ed[grp * NPB + lane];
                    float4 xq = *(const float4*)&xr[grp * 4];
                    float4 o;
                    STEPX(P, xq.x, th); o.x = P;
                    STEPX(P, xq.y, th); o.y = P;
                    STEPX(P, xq.z, th); o.z = P;
                    STEPX(P, xq.w, th); o.w = P;
                    *(float4*)&sb[lane * RS + grp * 4] = o;    // STS.128
                }
            }
        } else {
            // ========== drain warps (wid 3,7): sbuf tile t-2 -> global ==========
            if (t >= 2) {
                const int dt = t - 2;                 // == s row (HT == NH)
                const int pt = dt & 1;
                const int idx0 = (wid == 7) ? 512 : 0;
                const float* __restrict__ sb = sbuf + pt * NPB * RS;
                float* ob = outp + (((long long)b * NS + dt) * NN + g * NPB) * NH;
                float* sp = ob + TOTE;
                #pragma unroll
                for (int i = 0; i < 16; ++i) {
                    int idx = idx0 + i * 32 + lane;   // n = idx>>5, q = idx&31
                    int n = idx >> 5, q = idx & 31;
                    float4 v = *(const float4*)&sb[n * RS + q * 4];
                    float tn = thr[n];
                    float f0, f1, f2, f3;
                    asm("set.gt.f32.f32 %0, %1, %2;" : "=f"(f0) : "f"(v.x), "f"(tn));
                    asm("set.gt.f32.f32 %0, %1, %2;" : "=f"(f1) : "f"(v.y), "f"(tn));
                    asm("set.gt.f32.f32 %0, %1, %2;" : "=f"(f2) : "f"(v.z), "f"(tn));
                    asm("set.gt.f32.f32 %0, %1, %2;" : "=f"(f3) : "f"(v.w), "f"(tn));
                    float4 o = make_float4(v.x * f0, v.y * f1, v.z * f2, v.w * f3);
                    float4 k = make_float4(f0, f1, f2, f3);
                    *(float4*)(ob + n * NH + q * 4) = o;       // STG.128 coalesced
                    *(float4*)(sp + n * NH + q * 4) = k;
                }
            }
        }
        __syncthreads();
    }
}

extern "C" void kernel_launch(void* const* d_in, const int* in_sizes, int n_in,
                              void* d_out, int out_size)
{
    const float* inputs   = (const float*)d_in[0];  // [B,S,H]
    const float* threshes = (const float*)d_in[1];  // [N]
    const float* acc0     = (const float*)d_in[2];  // [B,N]
    float* out = (float*)d_out;                     // outs then spikes (f32)

    cudaFuncSetAttribute(lif_kernel,
                         cudaFuncAttributeMaxDynamicSharedMemorySize,
                         SMEM_BYTES);
    lif_kernel<<<NB * 2, 256, SMEM_BYTES>>>(inputs, threshes, acc0, out);
}